// round 4
// baseline (speedup 1.0000x reference)
#include <cuda_runtime.h>

// ---------------- problem constants ----------------------------------------
#define NMAX 100000
#define EMAX 1600000
#define NGRP 64
#define NB3  148          // fused-tail persistent grid (1 block/SM guaranteed)
#define NT3  512
#define GS3  (NB3 * NT3)  // 75776 threads

// ---------------- scratch (__device__ globals) -----------------------------
__device__ float2   g_kqvv[NMAX * 16];   // per node 32 floats: k0..k4 @0, (q s,v s) @8+2s
__device__ float4   g_aggv[NMAX * 2];    // per node 8 floats: conv1 agg in [0..5)
__device__ float    g_e2[EMAX];          // per-edge conv2 edge projection
__device__ float4   g_kqv2[NMAX];        // conv2 node proj (k2,q2,v2,_)
__device__ float    g_gsum[NGRP * 5];
__device__ float    g_gsq[NGRP * 5];
__device__ float    g_gcnt[NGRP];
__device__ unsigned g_bar;               // grid barrier counter (reset by K1)

__device__ __forceinline__ float fast_sigmoid(float z) {
    return 1.0f / (1.0f + __expf(-z));
}

// ---- packed f32x2 helpers (ptxas won't emit FFMA2/FADD2 from C++) ---------
__device__ __forceinline__ unsigned long long pack2(float a, float b) {
    unsigned long long r;
    asm("mov.b64 %0, {%1, %2};" : "=l"(r) : "f"(a), "f"(b));
    return r;
}
__device__ __forceinline__ void unpack2(unsigned long long v, float& a, float& b) {
    asm("mov.b64 {%0, %1}, %2;" : "=f"(a), "=f"(b) : "l"(v));
}
__device__ __forceinline__ void fma2(unsigned long long& d,
                                     unsigned long long a, unsigned long long b) {
    asm("fma.rn.f32x2 %0, %1, %2, %0;" : "+l"(d) : "l"(a), "l"(b));
}
__device__ __forceinline__ unsigned long long add2(unsigned long long a,
                                                   unsigned long long b) {
    unsigned long long r;
    asm("add.rn.f32x2 %0, %1, %2;" : "=l"(r) : "l"(a), "l"(b));
    return r;
}

// ---------------------------------------------------------------------------
// K1: conv1 node projections ([N,256]x[256,20] GEMM), warp-per-node.
// Lane l owns x columns l*8..l*8+7; weights live in 80 u64 registers (f32x2).
// Packed accumulators are stored to smem directly (no unpack) and 20 lanes
// transpose-reduce. Block 0 also zeroes the gnorm stats and the grid barrier.
__global__ __launch_bounds__(256) void node_proj1(
    const float* __restrict__ x,
    const float* __restrict__ Wk, const float* __restrict__ bk,
    const float* __restrict__ Wq, const float* __restrict__ bq,
    const float* __restrict__ Wv, const float* __restrict__ bv,
    const float* __restrict__ Ws, const float* __restrict__ bs,
    int N)
{
    __shared__ float sW[256 * 21];                       // stride 21: 4-way max conflict
    __shared__ __align__(16) float sred[8 * 32 * 20];

    int tid  = threadIdx.x;
    int lane = tid & 31;
    int wid  = tid >> 5;

    if (blockIdx.x == 0) {                               // fold zero_stats + bar reset
        for (int i = tid; i < NGRP * 5; i += 256) { g_gsum[i] = 0.f; g_gsq[i] = 0.f; }
        if (tid < NGRP) g_gcnt[tid] = 0.f;
        if (tid == 0)   g_bar = 0u;
    }

    for (int i = tid; i < 256 * 20; i += 256) {
        int c = i / 20, h = i % 20;
        float v;
        if (h < 5)       v = Wk[c * 5 + h];
        else if (h < 10) v = Wq[c * 5 + h - 5];
        else if (h < 15) v = Wv[c * 5 + h - 10];
        else             v = Ws[c * 5 + h - 15];
        sW[c * 21 + h] = v;
    }
    __syncthreads();

    unsigned long long w2[80];
#pragma unroll
    for (int i = 0; i < 8; i++) {
        int c = lane * 8 + i;
#pragma unroll
        for (int p = 0; p < 10; p++)
            w2[i * 10 + p] = pack2(sW[c * 21 + 2 * p], sW[c * 21 + 2 * p + 1]);
    }

    float blane = 0.f;
    if (lane < 5)       blane = __ldg(&bk[lane]);
    else if (lane < 10) blane = __ldg(&bq[lane - 5]);
    else if (lane < 15) blane = __ldg(&bv[lane - 10]);
    else if (lane < 20) blane = __ldg(&bs[lane - 15]);

    float* myred = &sred[wid * 640];
    float* kq  = (float*)g_kqvv;
    float* ag  = (float*)g_aggv;

    int warp    = blockIdx.x * 8 + wid;
    int wstride = gridDim.x * 8;

    int n = warp;
    float4 a0, a1;
    if (n < N) {
        const float4* xr = (const float4*)(x + (size_t)n * 256 + lane * 8);
        a0 = __ldg(xr); a1 = __ldg(xr + 1);
    }

    while (n < N) {
        float4 c0 = a0, c1 = a1;
        int nn = n + wstride;
        if (nn < N) {
            const float4* xr = (const float4*)(x + (size_t)nn * 256 + lane * 8);
            a0 = __ldg(xr); a1 = __ldg(xr + 1);
        }

        unsigned long long acc2[10];
#pragma unroll
        for (int p = 0; p < 10; p++) acc2[p] = 0ull;

        float xv[8] = {c0.x, c0.y, c0.z, c0.w, c1.x, c1.y, c1.z, c1.w};
#pragma unroll
        for (int i = 0; i < 8; i++) {
            unsigned long long xv2 = pack2(xv[i], xv[i]);
#pragma unroll
            for (int p = 0; p < 10; p++)
                fma2(acc2[p], xv2, w2[i * 10 + p]);
        }

        // store packed pairs straight to smem (20 floats = 5 x 16B)
        ulonglong2* dst2 = (ulonglong2*)(myred + lane * 20);
#pragma unroll
        for (int q = 0; q < 5; q++)
            dst2[q] = make_ulonglong2(acc2[2 * q], acc2[2 * q + 1]);
        __syncwarp();

        if (lane < 20) {
            float s0 = 0.f, s1 = 0.f, s2 = 0.f, s3 = 0.f;
#pragma unroll
            for (int l = 0; l < 32; l += 4) {
                s0 += myred[(l + 0) * 20 + lane];
                s1 += myred[(l + 1) * 20 + lane];
                s2 += myred[(l + 2) * 20 + lane];
                s3 += myred[(l + 3) * 20 + lane];
            }
            float val = (s0 + s1) + (s2 + s3) + blane;
            // scatter into the interleaved node row (32 floats / node)
            if (lane < 5)        kq[(size_t)n * 32 + lane] = val;                 // k_s
            else if (lane < 10)  kq[(size_t)n * 32 + 8 + 2 * (lane - 5)] = val;   // q_s
            else if (lane < 15)  kq[(size_t)n * 32 + 9 + 2 * (lane - 10)] = val;  // v_s
            else                 ag[(size_t)n * 8 + (lane - 15)] = val;           // skip
        }
        __syncwarp();
        n = nn;
    }
}

// ---------------------------------------------------------------------------
// K2: fused conv1 edge pass + conv2 edge projection.
// 8 lanes/edge. GEMV outputs packed as 3 f32x2 pairs: [e0,e1][e2,e3][e4,e2'].
// After a 3-level packed butterfly, lanes 0..4 gather (k_s | q_s,v_s as one
// LDG.64), gate, and messages are combined into ONE float4 atomic + ONE
// scalar atomic per edge (vs 5 scalar atomics before).
__global__ __launch_bounds__(256) void edge_pass1(
    const float* __restrict__ eatt, const int* __restrict__ ei,
    const float* __restrict__ We1, const float* __restrict__ be1,
    const float* __restrict__ We2, const float* __restrict__ be2,
    int E)
{
    int tid = threadIdx.x;
    int s   = tid & 7;
    int grp = (tid >> 3) & 3;
    unsigned gmask = 0xFFu << (grp * 8);   // all 8 lanes of group
    unsigned cmask = 0x1Fu << (grp * 8);   // lanes 0..4 of group

    // lane s holds We rows 4s..4s+3 as packed pairs
    unsigned long long w01[4], w23[4], w4e[4];
#pragma unroll
    for (int i = 0; i < 4; i++) {
        int c = s * 4 + i;
        w01[i] = pack2(__ldg(&We1[c * 5 + 0]), __ldg(&We1[c * 5 + 1]));
        w23[i] = pack2(__ldg(&We1[c * 5 + 2]), __ldg(&We1[c * 5 + 3]));
        w4e[i] = pack2(__ldg(&We1[c * 5 + 4]), __ldg(&We2[c]));
    }
    float beh  = (s < 5) ? __ldg(&be1[s]) : 0.f;
    float be2v = __ldg(be2);

    const float*  kqf = (const float*)g_kqvv;
    const float4* ea4 = (const float4*)eatt;
    float*        agf = (float*)g_aggv;

    int gid     = blockIdx.x * 32 + (tid >> 3);
    int gstride = gridDim.x * 32;

    for (int e = gid; e < E; e += gstride) {
        int src = __ldg(&ei[e]);
        int dst = __ldg(&ei[E + e]);
        float4 ea = __ldg(&ea4[(size_t)e * 8 + s]);

        unsigned long long p01 = 0ull, p23 = 0ull, p4e = 0ull;
        float xs[4] = {ea.x, ea.y, ea.z, ea.w};
#pragma unroll
        for (int i = 0; i < 4; i++) {
            unsigned long long xv2 = pack2(xs[i], xs[i]);
            fma2(p01, xv2, w01[i]);
            fma2(p23, xv2, w23[i]);
            fma2(p4e, xv2, w4e[i]);
        }
#pragma unroll
        for (int off = 4; off > 0; off >>= 1) {
            p01 = add2(p01, __shfl_xor_sync(gmask, p01, off, 8));
            p23 = add2(p23, __shfl_xor_sync(gmask, p23, off, 8));
            p4e = add2(p4e, __shfl_xor_sync(gmask, p4e, off, 8));
        }
        float e0, e1v, e2v, e3v, e4v, ec2;
        unpack2(p01, e0, e1v);
        unpack2(p23, e2v, e3v);
        unpack2(p4e, e4v, ec2);

        if (s == 5) {
            g_e2[e] = ec2 + be2v;
        } else if (s < 5) {
            float eh = (s == 0) ? e0 : (s == 1) ? e1v : (s == 2) ? e2v
                                     : (s == 3) ? e3v : e4v;
            eh += beh;
            float  k  = __ldg(&kqf[(size_t)dst * 32 + s]);
            float2 qv = __ldg(&g_kqvv[(size_t)src * 16 + 4 + s]);
            float gate = fast_sigmoid(k + qv.x + 2.f * eh);
            float msg  = gate * (qv.y + eh);
            float m1 = __shfl_sync(cmask, msg, 1, 8);
            float m2 = __shfl_sync(cmask, msg, 2, 8);
            float m3 = __shfl_sync(cmask, msg, 3, 8);
            if (s == 0)
                atomicAdd(&g_aggv[(size_t)dst * 2], make_float4(msg, m1, m2, m3));
            else if (s == 4)
                atomicAdd(&agf[(size_t)dst * 8 + 4], msg);
        }
    }
}

// ---------------------------------------------------------------------------
// software grid barrier (all NB3 blocks guaranteed co-resident)
__device__ __forceinline__ void grid_barrier(unsigned target)
{
    __syncthreads();
    if (threadIdx.x == 0) {
        __threadfence();
        atomicAdd(&g_bar, 1u);
        while (*(volatile unsigned*)&g_bar < target) { }
        __threadfence();
    }
    __syncthreads();
}

// ---------------------------------------------------------------------------
// K3: fused tail — gnorm stats -> A,B -> norm+relu+proj2 -> edge pass2 ->
// final sigmoid, separated by grid barriers. Cross-phase global reads use
// __ldcg to bypass (potentially stale) L1.
__global__ __launch_bounds__(NT3) void fused_tail(
    const int* __restrict__ batch, const int* __restrict__ ei,
    const float* __restrict__ gw, const float* __restrict__ gb,
    const float* __restrict__ gms,
    const float* __restrict__ Wk2, const float* __restrict__ bk2,
    const float* __restrict__ Wq2, const float* __restrict__ bq2,
    const float* __restrict__ Wv2, const float* __restrict__ bv2,
    const float* __restrict__ Ws2, const float* __restrict__ b2,
    float* __restrict__ out, int N, int E)
{
    __shared__ float ssum[NGRP * 5], ssq[NGRP * 5], scnt[NGRP];
    __shared__ float sA[NGRP * 5], sB[NGRP * 5];

    int tid  = threadIdx.x;
    int lane = tid & 31;
    const float* agf = (const float*)g_aggv;

    // ---- phase 1: group statistics -----------------------------------------
    for (int i = tid; i < NGRP * 5; i += NT3) { ssum[i] = 0.f; ssq[i] = 0.f; }
    if (tid < NGRP) scnt[tid] = 0.f;
    __syncthreads();

#pragma unroll
    for (int it = 0; it < 2; it++) {
        int n = blockIdx.x * NT3 + tid + it * GS3;
        bool valid = n < N;
        unsigned act = __ballot_sync(0xffffffffu, valid);
        if (act == 0) continue;                          // warp-uniform

        int g  = valid ? __ldg(&batch[n]) : 0;
        int g0 = __shfl_sync(0xffffffffu, g, 0);
        bool uni = __all_sync(0xffffffffu, valid && (g == g0));

        float v[5];
        float4 v4 = valid ? __ldg((const float4*)(agf + (size_t)n * 8))
                          : make_float4(0.f, 0.f, 0.f, 0.f);
        float  v5 = valid ? __ldg(agf + (size_t)n * 8 + 4) : 0.f;
        v[0] = v4.x; v[1] = v4.y; v[2] = v4.z; v[3] = v4.w; v[4] = v5;

        if (uni) {
#pragma unroll
            for (int h = 0; h < 5; h++) {
                float sv = v[h], sq = v[h] * v[h];
#pragma unroll
                for (int off = 16; off > 0; off >>= 1) {
                    sv += __shfl_xor_sync(0xffffffffu, sv, off);
                    sq += __shfl_xor_sync(0xffffffffu, sq, off);
                }
                if (lane == 0) {
                    atomicAdd(&ssum[g0 * 5 + h], sv);
                    atomicAdd(&ssq[g0 * 5 + h], sq);
                }
            }
            if (lane == 0) atomicAdd(&scnt[g0], 32.f);
        } else if (valid) {
#pragma unroll
            for (int h = 0; h < 5; h++) {
                atomicAdd(&ssum[g * 5 + h], v[h]);
                atomicAdd(&ssq[g * 5 + h], v[h] * v[h]);
            }
            atomicAdd(&scnt[g], 1.f);
        }
    }
    __syncthreads();
    for (int i = tid; i < NGRP * 5; i += NT3) {
        atomicAdd(&g_gsum[i], ssum[i]);
        atomicAdd(&g_gsq[i],  ssq[i]);
    }
    if (tid < NGRP) atomicAdd(&g_gcnt[tid], scnt[tid]);

    grid_barrier(1u * NB3);

    // ---- phase 2: per-group affine (A*x + B), redundant per block ----------
    if (tid < NGRP * 5) {
        int g = tid / 5, h = tid % 5;
        float cnt  = fmaxf(__ldcg(&g_gcnt[g]), 1.f);
        float mean = __ldcg(&g_gsum[tid]) / cnt;
        float ex2  = __ldcg(&g_gsq[tid])  / cnt;
        float ms   = __ldg(&gms[h]);
        float d    = mean * ms;
        float var  = ex2 - 2.f * d * mean + d * d;
        float inv  = rsqrtf(var + 1e-5f);
        float wv   = __ldg(&gw[h]);
        sA[tid] = wv * inv;
        sB[tid] = __ldg(&gb[h]) - wv * inv * d;
    }
    __syncthreads();

    // ---- phase 3: norm + relu + conv2 node projections ---------------------
    float k2b = __ldg(bk2), q2b = __ldg(bq2), v2b = __ldg(bv2), s2b = __ldg(b2);
    float wk[5], wq[5], wv5[5], wsk[5];
#pragma unroll
    for (int h = 0; h < 5; h++) {
        wk[h]  = __ldg(&Wk2[h]); wq[h]  = __ldg(&Wq2[h]);
        wv5[h] = __ldg(&Wv2[h]); wsk[h] = __ldg(&Ws2[h]);
    }
#pragma unroll
    for (int it = 0; it < 2; it++) {
        int n = blockIdx.x * NT3 + tid + it * GS3;
        if (n < N) {
            int g = __ldg(&batch[n]);
            float4 a4 = __ldg((const float4*)(agf + (size_t)n * 8));
            float  a5 = __ldg(agf + (size_t)n * 8 + 4);
            float av[5] = {a4.x, a4.y, a4.z, a4.w, a5};
            float k2 = k2b, q2 = q2b, v2 = v2b, s2 = s2b;
#pragma unroll
            for (int h = 0; h < 5; h++) {
                float hv = fmaxf(fmaf(sA[g * 5 + h], av[h], sB[g * 5 + h]), 0.f);
                k2 = fmaf(hv, wk[h],  k2);
                q2 = fmaf(hv, wq[h],  q2);
                v2 = fmaf(hv, wv5[h], v2);
                s2 = fmaf(hv, wsk[h], s2);
            }
            g_kqv2[n] = make_float4(k2, q2, v2, 0.f);
            out[n]    = s2;
        }
    }

    grid_barrier(2u * NB3);

    // ---- phase 4: conv2 edge pass (2-wide for MLP) --------------------------
    {
        int base = blockIdx.x * NT3 + tid;
        for (int e = base; e < E; e += 2 * GS3) {
            int eb = e + GS3;
            bool hb = eb < E;
            int sa = __ldg(&ei[e]),  da = __ldg(&ei[E + e]);
            int sb = hb ? __ldg(&ei[eb]) : 0;
            int db = hb ? __ldg(&ei[E + eb]) : 0;
            float eva = __ldg(&g_e2[e]);
            float evb = hb ? __ldg(&g_e2[eb]) : 0.f;
            float4 da4 = __ldcg(&g_kqv2[da]);
            float4 sa4 = __ldcg(&g_kqv2[sa]);
            float4 db4 = hb ? __ldcg(&g_kqv2[db]) : make_float4(0, 0, 0, 0);
            float4 sb4 = hb ? __ldcg(&g_kqv2[sb]) : make_float4(0, 0, 0, 0);
            float ga = fast_sigmoid(da4.x + sa4.y + 2.f * eva);
            atomicAdd(&out[da], ga * (sa4.z + eva));
            if (hb) {
                float gbv = fast_sigmoid(db4.x + sb4.y + 2.f * evb);
                atomicAdd(&out[db], gbv * (sb4.z + evb));
            }
        }
    }

    grid_barrier(3u * NB3);

    // ---- phase 5: final sigmoid --------------------------------------------
#pragma unroll
    for (int it = 0; it < 2; it++) {
        int n = blockIdx.x * NT3 + tid + it * GS3;
        if (n < N) out[n] = fast_sigmoid(__ldcg(&out[n]));
    }
}

// ---------------------------------------------------------------------------
extern "C" void kernel_launch(void* const* d_in, const int* in_sizes, int n_in,
                              void* d_out, int out_size)
{
    const float* x     = (const float*)d_in[0];
    const float* eatt  = (const float*)d_in[1];
    const int*   ei    = (const int*)d_in[2];
    const int*   batch = (const int*)d_in[3];
    const float* Wk1 = (const float*)d_in[4];
    const float* bk1 = (const float*)d_in[5];
    const float* Wq1 = (const float*)d_in[6];
    const float* bq1 = (const float*)d_in[7];
    const float* Wv1 = (const float*)d_in[8];
    const float* bv1 = (const float*)d_in[9];
    const float* We1 = (const float*)d_in[10];
    const float* be1 = (const float*)d_in[11];
    const float* Ws1 = (const float*)d_in[12];
    const float* b1  = (const float*)d_in[13];
    const float* gw  = (const float*)d_in[14];
    const float* gb  = (const float*)d_in[15];
    const float* gms = (const float*)d_in[16];
    const float* Wk2 = (const float*)d_in[17];
    const float* bk2 = (const float*)d_in[18];
    const float* Wq2 = (const float*)d_in[19];
    const float* bq2 = (const float*)d_in[20];
    const float* Wv2 = (const float*)d_in[21];
    const float* bv2 = (const float*)d_in[22];
    const float* We2 = (const float*)d_in[23];
    const float* be2 = (const float*)d_in[24];
    const float* Ws2 = (const float*)d_in[25];
    const float* b2  = (const float*)d_in[26];
    float* out = (float*)d_out;

    int N = in_sizes[3];
    int E = in_sizes[2] / 2;
    if (N > NMAX) N = NMAX;
    if (E > EMAX) E = EMAX;

    node_proj1<<<148, 256>>>(x, Wk1, bk1, Wq1, bq1, Wv1, bv1, Ws1, b1, N);
    edge_pass1<<<1184, 256>>>(eatt, ei, We1, be1, We2, be2, E);
    fused_tail<<<NB3, NT3>>>(batch, ei, gw, gb, gms,
                             Wk2, bk2, Wq2, bq2, Wv2, bv2, Ws2, b2,
                             out, N, E);
}

// round 5
// speedup vs baseline: 1.1758x; 1.1758x over previous
#include <cuda_runtime.h>

// ---------------- problem constants ----------------------------------------
#define NMAX 100000
#define EMAX 1600000
#define NGRP 64
#define NB3  148          // fused-tail persistent grid (1 block/SM guaranteed)
#define NT3  512
#define GS3  (NB3 * NT3)

// ---------------- scratch (__device__ globals) -----------------------------
__device__ float2   g_kqvv[NMAX * 16];   // per node 32 f: k0..4 @0, (q_s,v_s) @8+2s
__device__ float4   g_aggv[NMAX * 2];    // per node 8 f: conv1 agg in [0..5)
__device__ float    g_e2[EMAX];          // per-edge conv2 edge projection
__device__ float4   g_kqv2[NMAX];        // conv2 node proj (k2,q2,v2,_)
__device__ float    g_gsum[NGRP * 5];
__device__ float    g_gsq[NGRP * 5];
__device__ float    g_gcnt[NGRP];
__device__ unsigned g_bar;               // grid barrier counter (reset by K1)

__device__ __forceinline__ float fast_sigmoid(float z) {
    return 1.0f / (1.0f + __expf(-z));
}

// ---- packed f32x2 helpers (ptxas won't emit FFMA2/FADD2 from C++) ---------
__device__ __forceinline__ unsigned long long pack2(float a, float b) {
    unsigned long long r;
    asm("mov.b64 %0, {%1, %2};" : "=l"(r) : "f"(a), "f"(b));
    return r;
}
__device__ __forceinline__ void unpack2(unsigned long long v, float& a, float& b) {
    asm("mov.b64 {%0, %1}, %2;" : "=f"(a), "=f"(b) : "l"(v));
}
__device__ __forceinline__ void fma2(unsigned long long& d,
                                     unsigned long long a, unsigned long long b) {
    asm("fma.rn.f32x2 %0, %1, %2, %0;" : "+l"(d) : "l"(a), "l"(b));
}
__device__ __forceinline__ unsigned long long add2(unsigned long long a,
                                                   unsigned long long b) {
    unsigned long long r;
    asm("add.rn.f32x2 %0, %1, %2;" : "=l"(r) : "l"(a), "l"(b));
    return r;
}

// ---------------------------------------------------------------------------
// K1: conv1 node projections ([N,256]x[256,20] GEMM).
// Warp processes TWO nodes per iteration for ILP (occupancy is register-bound
// at 1 block/SM, so latency is hidden with independent streams instead).
// Lane l owns x columns l*8..l*8+7; weights = 80 u64 regs (f32x2 pairs).
// smem is overlaid: weight staging (5376 f) then transpose buffers (10240 f).
__global__ __launch_bounds__(256, 1) void node_proj1(
    const float* __restrict__ x,
    const float* __restrict__ Wk, const float* __restrict__ bk,
    const float* __restrict__ Wq, const float* __restrict__ bq,
    const float* __restrict__ Wv, const float* __restrict__ bv,
    const float* __restrict__ Ws, const float* __restrict__ bs,
    int N)
{
    __shared__ __align__(16) float sbuf[10240];   // 40KB, dual-purpose

    int tid  = threadIdx.x;
    int lane = tid & 31;
    int wid  = tid >> 5;

    if (blockIdx.x == 0) {                        // fold zero_stats + bar reset
        for (int i = tid; i < NGRP * 5; i += 256) { g_gsum[i] = 0.f; g_gsq[i] = 0.f; }
        if (tid < NGRP) g_gcnt[tid] = 0.f;
        if (tid == 0)   g_bar = 0u;
    }

    // stage combined weights [c][h] with stride 21
    for (int i = tid; i < 256 * 20; i += 256) {
        int c = i / 20, h = i % 20;
        float v;
        if (h < 5)       v = Wk[c * 5 + h];
        else if (h < 10) v = Wq[c * 5 + h - 5];
        else if (h < 15) v = Wv[c * 5 + h - 10];
        else             v = Ws[c * 5 + h - 15];
        sbuf[c * 21 + h] = v;
    }
    __syncthreads();

    unsigned long long w2[80];
#pragma unroll
    for (int i = 0; i < 8; i++) {
        int c = lane * 8 + i;
#pragma unroll
        for (int p = 0; p < 10; p++)
            w2[i * 10 + p] = pack2(sbuf[c * 21 + 2 * p], sbuf[c * 21 + 2 * p + 1]);
    }
    __syncthreads();                              // all w2 reads done: reuse sbuf

    float blane = 0.f;
    if (lane < 5)       blane = __ldg(&bk[lane]);
    else if (lane < 10) blane = __ldg(&bq[lane - 5]);
    else if (lane < 15) blane = __ldg(&bv[lane - 10]);
    else if (lane < 20) blane = __ldg(&bs[lane - 15]);

    float* redA = &sbuf[wid * 1280];
    float* redB = redA + 640;
    float* kq   = (float*)g_kqvv;
    float* ag   = (float*)g_aggv;

    int warp = blockIdx.x * 8 + wid;
    int step = gridDim.x * 8 * 2;

    int n = warp * 2;
    float4 a0A, a1A, a0B, a1B;
    if (n < N) {
        const float4* xr = (const float4*)(x + (size_t)n * 256 + lane * 8);
        a0A = __ldg(xr); a1A = __ldg(xr + 1);
    }
    if (n + 1 < N) {
        const float4* xr = (const float4*)(x + (size_t)(n + 1) * 256 + lane * 8);
        a0B = __ldg(xr); a1B = __ldg(xr + 1);
    }

    while (n < N) {
        float4 cA0 = a0A, cA1 = a1A, cB0 = a0B, cB1 = a1B;
        bool hb = (n + 1) < N;
        int nn = n + step;
        if (nn < N) {
            const float4* xr = (const float4*)(x + (size_t)nn * 256 + lane * 8);
            a0A = __ldg(xr); a1A = __ldg(xr + 1);
        }
        if (nn + 1 < N) {
            const float4* xr = (const float4*)(x + (size_t)(nn + 1) * 256 + lane * 8);
            a0B = __ldg(xr); a1B = __ldg(xr + 1);
        }

        unsigned long long accA[10], accB[10];
#pragma unroll
        for (int p = 0; p < 10; p++) { accA[p] = 0ull; accB[p] = 0ull; }

        float xA[8] = {cA0.x, cA0.y, cA0.z, cA0.w, cA1.x, cA1.y, cA1.z, cA1.w};
        float xB[8] = {cB0.x, cB0.y, cB0.z, cB0.w, cB1.x, cB1.y, cB1.z, cB1.w};
#pragma unroll
        for (int i = 0; i < 8; i++) {
            unsigned long long xa = pack2(xA[i], xA[i]);
            unsigned long long xb = pack2(xB[i], xB[i]);
#pragma unroll
            for (int p = 0; p < 10; p++) {
                fma2(accA[p], xa, w2[i * 10 + p]);
                fma2(accB[p], xb, w2[i * 10 + p]);
            }
        }

        // store both packed accumulator sets (20 f each = 5 x 16B)
        {
            ulonglong2* dA = (ulonglong2*)(redA + lane * 20);
            ulonglong2* dB = (ulonglong2*)(redB + lane * 20);
#pragma unroll
            for (int q = 0; q < 5; q++) {
                dA[q] = make_ulonglong2(accA[2 * q], accA[2 * q + 1]);
                dB[q] = make_ulonglong2(accB[2 * q], accB[2 * q + 1]);
            }
        }
        __syncwarp();

        if (lane < 20) {
            float sA0 = 0.f, sA1 = 0.f, sB0 = 0.f, sB1 = 0.f;
#pragma unroll
            for (int l = 0; l < 32; l += 2) {
                sA0 += redA[(l + 0) * 20 + lane];
                sA1 += redA[(l + 1) * 20 + lane];
                sB0 += redB[(l + 0) * 20 + lane];
                sB1 += redB[(l + 1) * 20 + lane];
            }
            float vA = sA0 + sA1 + blane;
            float vB = sB0 + sB1 + blane;
            if (lane < 5) {
                kq[(size_t)n * 32 + lane] = vA;
                if (hb) kq[(size_t)(n + 1) * 32 + lane] = vB;
            } else if (lane < 10) {
                kq[(size_t)n * 32 + 8 + 2 * (lane - 5)] = vA;
                if (hb) kq[(size_t)(n + 1) * 32 + 8 + 2 * (lane - 5)] = vB;
            } else if (lane < 15) {
                kq[(size_t)n * 32 + 9 + 2 * (lane - 10)] = vA;
                if (hb) kq[(size_t)(n + 1) * 32 + 9 + 2 * (lane - 10)] = vB;
            } else {
                ag[(size_t)n * 8 + (lane - 15)] = vA;
                if (hb) ag[(size_t)(n + 1) * 8 + (lane - 15)] = vB;
            }
        }
        __syncwarp();
        n = nn;
    }
}

// ---------------------------------------------------------------------------
// K2: fused conv1 edge pass + conv2 edge projection. 4 lanes per edge.
// Lane c owns eatt cols c*8..c*8+7 (2 coalesced float4 loads) with the We
// slice in 24 u64 regs. Packed 2-level butterfly gives every lane all 6
// outputs; lane c gates feature c, lane 3 additionally feature 4, lane 0
// stores e2 and issues the float4 message atomic.
__global__ __launch_bounds__(256) void edge_pass1(
    const float* __restrict__ eatt, const int* __restrict__ ei,
    const float* __restrict__ We1, const float* __restrict__ be1,
    const float* __restrict__ We2, const float* __restrict__ be2,
    int E)
{
    int tid = threadIdx.x;
    int c   = tid & 3;

    unsigned long long w01[8], w23[8], w4e[8];
#pragma unroll
    for (int i = 0; i < 8; i++) {
        int col = c * 8 + i;
        w01[i] = pack2(__ldg(&We1[col * 5 + 0]), __ldg(&We1[col * 5 + 1]));
        w23[i] = pack2(__ldg(&We1[col * 5 + 2]), __ldg(&We1[col * 5 + 3]));
        w4e[i] = pack2(__ldg(&We1[col * 5 + 4]), __ldg(&We2[col]));
    }
    float behc = __ldg(&be1[c]);
    float beh4 = __ldg(&be1[4]);
    float bec2 = __ldg(be2);

    const float*  kqf = (const float*)g_kqvv;
    const float4* ea4 = (const float4*)eatt;
    float*        agf = (float*)g_aggv;

    int gid     = blockIdx.x * 64 + (tid >> 2);
    int gstride = gridDim.x * 64;

    for (int e = gid; e < E; e += gstride) {
        int src = __ldg(&ei[e]);
        int dst = __ldg(&ei[E + e]);
        float4 ea0 = __ldg(&ea4[(size_t)e * 8 + c * 2]);
        float4 ea1 = __ldg(&ea4[(size_t)e * 8 + c * 2 + 1]);

        unsigned long long p01 = 0ull, p23 = 0ull, p4e = 0ull;
        float xs[8] = {ea0.x, ea0.y, ea0.z, ea0.w, ea1.x, ea1.y, ea1.z, ea1.w};
#pragma unroll
        for (int i = 0; i < 8; i++) {
            unsigned long long xv2 = pack2(xs[i], xs[i]);
            fma2(p01, xv2, w01[i]);
            fma2(p23, xv2, w23[i]);
            fma2(p4e, xv2, w4e[i]);
        }
#pragma unroll
        for (int off = 2; off > 0; off >>= 1) {
            p01 = add2(p01, __shfl_xor_sync(0xffffffffu, p01, off, 4));
            p23 = add2(p23, __shfl_xor_sync(0xffffffffu, p23, off, 4));
            p4e = add2(p4e, __shfl_xor_sync(0xffffffffu, p4e, off, 4));
        }
        float e0, e1f, e2f, e3f, e4f, ec2;
        unpack2(p01, e0, e1f);
        unpack2(p23, e2f, e3f);
        unpack2(p4e, e4f, ec2);

        // feature s = c for every lane
        float eh = ((c == 0) ? e0 : (c == 1) ? e1f : (c == 2) ? e2f : e3f) + behc;
        float  k  = __ldg(&kqf[(size_t)dst * 32 + c]);
        float2 qv = __ldg(&g_kqvv[(size_t)src * 16 + 4 + c]);
        float gate = fast_sigmoid(k + qv.x + 2.f * eh);
        float msg  = gate * (qv.y + eh);

        float m1 = __shfl_sync(0xffffffffu, msg, 1, 4);
        float m2 = __shfl_sync(0xffffffffu, msg, 2, 4);
        float m3 = __shfl_sync(0xffffffffu, msg, 3, 4);

        if (c == 3) {                 // feature 4 rider
            float eh4  = e4f + beh4;
            float k4   = __ldg(&kqf[(size_t)dst * 32 + 4]);
            float2 qv4 = __ldg(&g_kqvv[(size_t)src * 16 + 8]);
            float g4   = fast_sigmoid(k4 + qv4.x + 2.f * eh4);
            atomicAdd(&agf[(size_t)dst * 8 + 4], g4 * (qv4.y + eh4));
        } else if (c == 0) {
            g_e2[e] = ec2 + bec2;
            atomicAdd(&g_aggv[(size_t)dst * 2], make_float4(msg, m1, m2, m3));
        }
    }
}

// ---------------------------------------------------------------------------
__device__ __forceinline__ void grid_barrier(unsigned target)
{
    __syncthreads();
    if (threadIdx.x == 0) {
        __threadfence();
        atomicAdd(&g_bar, 1u);
        while (*(volatile unsigned*)&g_bar < target) { }
        __threadfence();
    }
    __syncthreads();
}

// ---------------------------------------------------------------------------
// K3: fused tail — gnorm stats -> A,B -> norm+relu+proj2 -> edge pass2 ->
// final sigmoid, separated by grid barriers.
__global__ __launch_bounds__(NT3) void fused_tail(
    const int* __restrict__ batch, const int* __restrict__ ei,
    const float* __restrict__ gw, const float* __restrict__ gb,
    const float* __restrict__ gms,
    const float* __restrict__ Wk2, const float* __restrict__ bk2,
    const float* __restrict__ Wq2, const float* __restrict__ bq2,
    const float* __restrict__ Wv2, const float* __restrict__ bv2,
    const float* __restrict__ Ws2, const float* __restrict__ b2,
    float* __restrict__ out, int N, int E)
{
    __shared__ float ssum[NGRP * 5], ssq[NGRP * 5], scnt[NGRP];
    __shared__ float sA[NGRP * 5], sB[NGRP * 5];

    int tid  = threadIdx.x;
    int lane = tid & 31;
    const float* agf = (const float*)g_aggv;

    // ---- phase 1: group statistics -----------------------------------------
    for (int i = tid; i < NGRP * 5; i += NT3) { ssum[i] = 0.f; ssq[i] = 0.f; }
    if (tid < NGRP) scnt[tid] = 0.f;
    __syncthreads();

#pragma unroll
    for (int it = 0; it < 2; it++) {
        int n = blockIdx.x * NT3 + tid + it * GS3;
        bool valid = n < N;
        unsigned act = __ballot_sync(0xffffffffu, valid);
        if (act == 0) continue;

        int g  = valid ? __ldg(&batch[n]) : 0;
        int g0 = __shfl_sync(0xffffffffu, g, 0);
        bool uni = __all_sync(0xffffffffu, valid && (g == g0));

        float v[5];
        float4 v4 = valid ? __ldg((const float4*)(agf + (size_t)n * 8))
                          : make_float4(0.f, 0.f, 0.f, 0.f);
        float  v5 = valid ? __ldg(agf + (size_t)n * 8 + 4) : 0.f;
        v[0] = v4.x; v[1] = v4.y; v[2] = v4.z; v[3] = v4.w; v[4] = v5;

        if (uni) {
#pragma unroll
            for (int h = 0; h < 5; h++) {
                float sv = v[h], sq = v[h] * v[h];
#pragma unroll
                for (int off = 16; off > 0; off >>= 1) {
                    sv += __shfl_xor_sync(0xffffffffu, sv, off);
                    sq += __shfl_xor_sync(0xffffffffu, sq, off);
                }
                if (lane == 0) {
                    atomicAdd(&ssum[g0 * 5 + h], sv);
                    atomicAdd(&ssq[g0 * 5 + h], sq);
                }
            }
            if (lane == 0) atomicAdd(&scnt[g0], 32.f);
        } else if (valid) {
#pragma unroll
            for (int h = 0; h < 5; h++) {
                atomicAdd(&ssum[g * 5 + h], v[h]);
                atomicAdd(&ssq[g * 5 + h], v[h] * v[h]);
            }
            atomicAdd(&scnt[g], 1.f);
        }
    }
    __syncthreads();
    for (int i = tid; i < NGRP * 5; i += NT3) {
        atomicAdd(&g_gsum[i], ssum[i]);
        atomicAdd(&g_gsq[i],  ssq[i]);
    }
    if (tid < NGRP) atomicAdd(&g_gcnt[tid], scnt[tid]);

    grid_barrier(1u * NB3);

    // ---- phase 2: per-group affine ------------------------------------------
    if (tid < NGRP * 5) {
        int g = tid / 5, h = tid % 5;
        float cnt  = fmaxf(__ldcg(&g_gcnt[g]), 1.f);
        float mean = __ldcg(&g_gsum[tid]) / cnt;
        float ex2  = __ldcg(&g_gsq[tid])  / cnt;
        float ms   = __ldg(&gms[h]);
        float d    = mean * ms;
        float var  = ex2 - 2.f * d * mean + d * d;
        float inv  = rsqrtf(var + 1e-5f);
        float wv   = __ldg(&gw[h]);
        sA[tid] = wv * inv;
        sB[tid] = __ldg(&gb[h]) - wv * inv * d;
    }
    __syncthreads();

    // ---- phase 3: norm + relu + conv2 node projections ----------------------
    float k2b = __ldg(bk2), q2b = __ldg(bq2), v2b = __ldg(bv2), s2b = __ldg(b2);
    float wk[5], wq[5], wv5[5], wsk[5];
#pragma unroll
    for (int h = 0; h < 5; h++) {
        wk[h]  = __ldg(&Wk2[h]); wq[h]  = __ldg(&Wq2[h]);
        wv5[h] = __ldg(&Wv2[h]); wsk[h] = __ldg(&Ws2[h]);
    }
#pragma unroll
    for (int it = 0; it < 2; it++) {
        int n = blockIdx.x * NT3 + tid + it * GS3;
        if (n < N) {
            int g = __ldg(&batch[n]);
            float4 a4 = __ldg((const float4*)(agf + (size_t)n * 8));
            float  a5 = __ldg(agf + (size_t)n * 8 + 4);
            float av[5] = {a4.x, a4.y, a4.z, a4.w, a5};
            float k2 = k2b, q2 = q2b, v2 = v2b, s2 = s2b;
#pragma unroll
            for (int h = 0; h < 5; h++) {
                float hv = fmaxf(fmaf(sA[g * 5 + h], av[h], sB[g * 5 + h]), 0.f);
                k2 = fmaf(hv, wk[h],  k2);
                q2 = fmaf(hv, wq[h],  q2);
                v2 = fmaf(hv, wv5[h], v2);
                s2 = fmaf(hv, wsk[h], s2);
            }
            g_kqv2[n] = make_float4(k2, q2, v2, 0.f);
            out[n]    = s2;
        }
    }

    grid_barrier(2u * NB3);

    // ---- phase 4: conv2 edge pass (2-wide for MLP) ---------------------------
    {
        int base = blockIdx.x * NT3 + tid;
        for (int e = base; e < E; e += 2 * GS3) {
            int eb = e + GS3;
            bool hb = eb < E;
            int sa = __ldg(&ei[e]),  da = __ldg(&ei[E + e]);
            int sb = hb ? __ldg(&ei[eb]) : 0;
            int db = hb ? __ldg(&ei[E + eb]) : 0;
            float eva = __ldg(&g_e2[e]);
            float evb = hb ? __ldg(&g_e2[eb]) : 0.f;
            float4 da4 = __ldcg(&g_kqv2[da]);
            float4 sa4 = __ldcg(&g_kqv2[sa]);
            float4 db4 = hb ? __ldcg(&g_kqv2[db]) : make_float4(0, 0, 0, 0);
            float4 sb4 = hb ? __ldcg(&g_kqv2[sb]) : make_float4(0, 0, 0, 0);
            float ga = fast_sigmoid(da4.x + sa4.y + 2.f * eva);
            atomicAdd(&out[da], ga * (sa4.z + eva));
            if (hb) {
                float gbv = fast_sigmoid(db4.x + sb4.y + 2.f * evb);
                atomicAdd(&out[db], gbv * (sb4.z + evb));
            }
        }
    }

    grid_barrier(3u * NB3);

    // ---- phase 5: final sigmoid ----------------------------------------------
#pragma unroll
    for (int it = 0; it < 2; it++) {
        int n = blockIdx.x * NT3 + tid + it * GS3;
        if (n < N) out[n] = fast_sigmoid(__ldcg(&out[n]));
    }
}

// ---------------------------------------------------------------------------
extern "C" void kernel_launch(void* const* d_in, const int* in_sizes, int n_in,
                              void* d_out, int out_size)
{
    const float* x     = (const float*)d_in[0];
    const float* eatt  = (const float*)d_in[1];
    const int*   ei    = (const int*)d_in[2];
    const int*   batch = (const int*)d_in[3];
    const float* Wk1 = (const float*)d_in[4];
    const float* bk1 = (const float*)d_in[5];
    const float* Wq1 = (const float*)d_in[6];
    const float* bq1 = (const float*)d_in[7];
    const float* Wv1 = (const float*)d_in[8];
    const float* bv1 = (const float*)d_in[9];
    const float* We1 = (const float*)d_in[10];
    const float* be1 = (const float*)d_in[11];
    const float* Ws1 = (const float*)d_in[12];
    const float* b1  = (const float*)d_in[13];
    const float* gw  = (const float*)d_in[14];
    const float* gb  = (const float*)d_in[15];
    const float* gms = (const float*)d_in[16];
    const float* Wk2 = (const float*)d_in[17];
    const float* bk2 = (const float*)d_in[18];
    const float* Wq2 = (const float*)d_in[19];
    const float* bq2 = (const float*)d_in[20];
    const float* Wv2 = (const float*)d_in[21];
    const float* bv2 = (const float*)d_in[22];
    const float* We2 = (const float*)d_in[23];
    const float* be2 = (const float*)d_in[24];
    const float* Ws2 = (const float*)d_in[25];
    const float* b2  = (const float*)d_in[26];
    float* out = (float*)d_out;

    int N = in_sizes[3];
    int E = in_sizes[2] / 2;
    if (N > NMAX) N = NMAX;
    if (E > EMAX) E = EMAX;

    node_proj1<<<148, 256>>>(x, Wk1, bk1, Wq1, bq1, Wv1, bv1, Ws1, b1, N);
    edge_pass1<<<1184, 256>>>(eatt, ei, We1, be1, We2, be2, E);
    fused_tail<<<NB3, NT3>>>(batch, ei, gw, gb, gms,
                             Wk2, bk2, Wq2, bq2, Wv2, bv2, Ws2, b2,
                             out, N, E);
}

// round 6
// speedup vs baseline: 1.1830x; 1.0061x over previous
#include <cuda_runtime.h>

// ---------------- problem constants ----------------------------------------
#define NMAX 100000
#define EMAX 1600000
#define NGRP 64
#define NB3  148          // fused-tail persistent grid (1 block/SM guaranteed)
#define NT3  512
#define GS3  (NB3 * NT3)

// ---------------- scratch (__device__ globals) -----------------------------
__device__ float2   g_kqvv[NMAX * 16];   // per node 32 f: k0..4 @0, (q_s,v_s) @8+2s
__device__ float4   g_aggv[NMAX * 2];    // per node 8 f: conv1 agg in [0..5)
__device__ float    g_e2[EMAX];          // per-edge conv2 edge projection
__device__ float4   g_kqv2[NMAX];        // conv2 node proj (k2,q2,v2,_)
__device__ float    g_gsum[NGRP * 5];
__device__ float    g_gsq[NGRP * 5];
__device__ float    g_gcnt[NGRP];
__device__ unsigned g_bar;               // grid barrier counter (reset by K1)

__device__ __forceinline__ float fast_sigmoid(float z) {
    return 1.0f / (1.0f + __expf(-z));
}

// ---- packed f32x2 helpers (ptxas won't emit FFMA2/FADD2 from C++) ---------
__device__ __forceinline__ unsigned long long pack2(float a, float b) {
    unsigned long long r;
    asm("mov.b64 %0, {%1, %2};" : "=l"(r) : "f"(a), "f"(b));
    return r;
}
__device__ __forceinline__ void unpack2(unsigned long long v, float& a, float& b) {
    asm("mov.b64 {%0, %1}, %2;" : "=f"(a), "=f"(b) : "l"(v));
}
__device__ __forceinline__ void fma2(unsigned long long& d,
                                     unsigned long long a, unsigned long long b) {
    asm("fma.rn.f32x2 %0, %1, %2, %0;" : "+l"(d) : "l"(a), "l"(b));
}
__device__ __forceinline__ unsigned long long add2(unsigned long long a,
                                                   unsigned long long b) {
    unsigned long long r;
    asm("add.rn.f32x2 %0, %1, %2;" : "=l"(r) : "l"(a), "l"(b));
    return r;
}

// ---------------------------------------------------------------------------
// K1: conv1 node projections ([N,256]x[256,20] GEMM).
// A warp PAIR handles one node per iteration: warp r (r=0,1) covers columns
// r*128..r*128+127, lane owning 4 columns (40 u64 weight regs -> ~125 regs
// total -> 2 blocks/SM = 16 warps, vs 8 before). Each warp transpose-reduces
// its 32 partial rows in smem; warp 1 publishes a 20-float row, warp 0
// combines + scatters. Named barrier per pair synchronizes the handoff.
__global__ __launch_bounds__(256, 2) void node_proj1(
    const float* __restrict__ x,
    const float* __restrict__ Wk, const float* __restrict__ bk,
    const float* __restrict__ Wq, const float* __restrict__ bq,
    const float* __restrict__ Wv, const float* __restrict__ bv,
    const float* __restrict__ Ws, const float* __restrict__ bs,
    int N)
{
    __shared__ __align__(16) float sbuf[5376];    // weights staging, then 4x1320 pair bufs

    int tid  = threadIdx.x;
    int lane = tid & 31;
    int wid  = tid >> 5;
    int pr   = wid >> 1;          // pair 0..3
    int r    = wid & 1;           // role within pair

    if (blockIdx.x == 0) {
        for (int i = tid; i < NGRP * 5; i += 256) { g_gsum[i] = 0.f; g_gsq[i] = 0.f; }
        if (tid < NGRP) g_gcnt[tid] = 0.f;
        if (tid == 0)   g_bar = 0u;
    }

    // stage combined weights [c][h] with stride 21
    for (int i = tid; i < 256 * 20; i += 256) {
        int c = i / 20, h = i % 20;
        float v;
        if (h < 5)       v = Wk[c * 5 + h];
        else if (h < 10) v = Wq[c * 5 + h - 5];
        else if (h < 15) v = Wv[c * 5 + h - 10];
        else             v = Ws[c * 5 + h - 15];
        sbuf[c * 21 + h] = v;
    }
    __syncthreads();

    // lane-private weight slice: 4 columns x 10 h-pairs = 40 u64
    unsigned long long w2[40];
#pragma unroll
    for (int i = 0; i < 4; i++) {
        int c = r * 128 + lane * 4 + i;
#pragma unroll
        for (int p = 0; p < 10; p++)
            w2[i * 10 + p] = pack2(sbuf[c * 21 + 2 * p], sbuf[c * 21 + 2 * p + 1]);
    }
    __syncthreads();                              // weights consumed: reuse sbuf

    float blane = 0.f;
    if (lane < 5)       blane = __ldg(&bk[lane]);
    else if (lane < 10) blane = __ldg(&bq[lane - 5]);
    else if (lane < 15) blane = __ldg(&bv[lane - 10]);
    else if (lane < 20) blane = __ldg(&bs[lane - 15]);

    float* myred = &sbuf[pr * 1320 + r * 640];    // this warp's 32x20 partials
    float* xrow  = &sbuf[pr * 1320 + 1280];       // warp1 -> warp0 handoff row
    int bar_id = pr + 1;

    float* kq = (float*)g_kqvv;
    float* ag = (float*)g_aggv;

    int n    = blockIdx.x * 4 + pr;
    int step = gridDim.x * 4;

    float4 a0;
    if (n < N)
        a0 = __ldg((const float4*)(x + (size_t)n * 256 + r * 128 + lane * 4));

    while (n < N) {
        float4 cx = a0;
        int nn = n + step;
        if (nn < N)
            a0 = __ldg((const float4*)(x + (size_t)nn * 256 + r * 128 + lane * 4));

        unsigned long long acc2[10];
#pragma unroll
        for (int p = 0; p < 10; p++) acc2[p] = 0ull;

        float xv[4] = {cx.x, cx.y, cx.z, cx.w};
#pragma unroll
        for (int i = 0; i < 4; i++) {
            unsigned long long xa = pack2(xv[i], xv[i]);
#pragma unroll
            for (int p = 0; p < 10; p++)
                fma2(acc2[p], xa, w2[i * 10 + p]);
        }

        ulonglong2* dst2 = (ulonglong2*)(myred + lane * 20);
#pragma unroll
        for (int q = 0; q < 5; q++)
            dst2[q] = make_ulonglong2(acc2[2 * q], acc2[2 * q + 1]);
        __syncwarp();

        float redsum = 0.f;
        if (lane < 20) {
            float s0 = 0.f, s1 = 0.f;
#pragma unroll
            for (int l = 0; l < 32; l += 2) {
                s0 += myred[(l + 0) * 20 + lane];
                s1 += myred[(l + 1) * 20 + lane];
            }
            redsum = s0 + s1;
            if (r == 1) xrow[lane] = redsum;
        }
        asm volatile("bar.sync %0, %1;" :: "r"(bar_id), "r"(64) : "memory");

        if (r == 0 && lane < 20) {
            float val = redsum + xrow[lane] + blane;
            if (lane < 5)        kq[(size_t)n * 32 + lane] = val;
            else if (lane < 10)  kq[(size_t)n * 32 + 8 + 2 * (lane - 5)] = val;
            else if (lane < 15)  kq[(size_t)n * 32 + 9 + 2 * (lane - 10)] = val;
            else                 ag[(size_t)n * 8 + (lane - 15)] = val;
        }
        asm volatile("bar.sync %0, %1;" :: "r"(bar_id), "r"(64) : "memory");
        n = nn;
    }
}

// ---------------------------------------------------------------------------
// K2: fused conv1 edge pass + conv2 edge projection. 4 lanes per edge,
// TWO edges per iteration (software pipeline: all loads for both edges are
// issued before either GEMV, doubling the in-flight memory per warp).
__global__ __launch_bounds__(256) void edge_pass1(
    const float* __restrict__ eatt, const int* __restrict__ ei,
    const float* __restrict__ We1, const float* __restrict__ be1,
    const float* __restrict__ We2, const float* __restrict__ be2,
    int E)
{
    int tid = threadIdx.x;
    int c   = tid & 3;

    unsigned long long w01[8], w23[8], w4e[8];
#pragma unroll
    for (int i = 0; i < 8; i++) {
        int col = c * 8 + i;
        w01[i] = pack2(__ldg(&We1[col * 5 + 0]), __ldg(&We1[col * 5 + 1]));
        w23[i] = pack2(__ldg(&We1[col * 5 + 2]), __ldg(&We1[col * 5 + 3]));
        w4e[i] = pack2(__ldg(&We1[col * 5 + 4]), __ldg(&We2[col]));
    }
    float behc = __ldg(&be1[c]);
    float beh4 = __ldg(&be1[4]);
    float bec2 = __ldg(be2);

    const float*  kqf = (const float*)g_kqvv;
    const float4* ea4 = (const float4*)eatt;
    float*        agf = (float*)g_aggv;

    int gid     = blockIdx.x * 64 + (tid >> 2);
    int gstride = gridDim.x * 64;

    for (int e = gid; e < E; e += 2 * gstride) {
        int eb = e + gstride;
        bool hb = eb < E;

        // ---- issue ALL loads for both edges ------------------------------
        int srcA = __ldg(&ei[e]);
        int dstA = __ldg(&ei[E + e]);
        int srcB = hb ? __ldg(&ei[eb]) : srcA;
        int dstB = hb ? __ldg(&ei[E + eb]) : dstA;

        float4 a0 = __ldg(&ea4[(size_t)e * 8 + c * 2]);
        float4 a1 = __ldg(&ea4[(size_t)e * 8 + c * 2 + 1]);
        float4 b0 = hb ? __ldg(&ea4[(size_t)eb * 8 + c * 2])     : a0;
        float4 b1 = hb ? __ldg(&ea4[(size_t)eb * 8 + c * 2 + 1]) : a1;

        float  kA  = __ldg(&kqf[(size_t)dstA * 32 + c]);
        float2 qvA = __ldg(&g_kqvv[(size_t)srcA * 16 + 4 + c]);
        float  kB  = __ldg(&kqf[(size_t)dstB * 32 + c]);
        float2 qvB = __ldg(&g_kqvv[(size_t)srcB * 16 + 4 + c]);

        float k4A = 0.f, k4B = 0.f;
        float2 qv4A = make_float2(0.f, 0.f), qv4B = make_float2(0.f, 0.f);
        if (c == 3) {
            k4A  = __ldg(&kqf[(size_t)dstA * 32 + 4]);
            qv4A = __ldg(&g_kqvv[(size_t)srcA * 16 + 8]);
            k4B  = __ldg(&kqf[(size_t)dstB * 32 + 4]);
            qv4B = __ldg(&g_kqvv[(size_t)srcB * 16 + 8]);
        }

        // ---- GEMV for both edges ------------------------------------------
        unsigned long long pA01 = 0ull, pA23 = 0ull, pA4e = 0ull;
        unsigned long long pB01 = 0ull, pB23 = 0ull, pB4e = 0ull;
        float xsA[8] = {a0.x, a0.y, a0.z, a0.w, a1.x, a1.y, a1.z, a1.w};
        float xsB[8] = {b0.x, b0.y, b0.z, b0.w, b1.x, b1.y, b1.z, b1.w};
#pragma unroll
        for (int i = 0; i < 8; i++) {
            unsigned long long xa = pack2(xsA[i], xsA[i]);
            unsigned long long xb = pack2(xsB[i], xsB[i]);
            fma2(pA01, xa, w01[i]); fma2(pA23, xa, w23[i]); fma2(pA4e, xa, w4e[i]);
            fma2(pB01, xb, w01[i]); fma2(pB23, xb, w23[i]); fma2(pB4e, xb, w4e[i]);
        }
#pragma unroll
        for (int off = 2; off > 0; off >>= 1) {
            pA01 = add2(pA01, __shfl_xor_sync(0xffffffffu, pA01, off, 4));
            pA23 = add2(pA23, __shfl_xor_sync(0xffffffffu, pA23, off, 4));
            pA4e = add2(pA4e, __shfl_xor_sync(0xffffffffu, pA4e, off, 4));
            pB01 = add2(pB01, __shfl_xor_sync(0xffffffffu, pB01, off, 4));
            pB23 = add2(pB23, __shfl_xor_sync(0xffffffffu, pB23, off, 4));
            pB4e = add2(pB4e, __shfl_xor_sync(0xffffffffu, pB4e, off, 4));
        }

        float eA0, eA1, eA2, eA3, eA4, eAc2;
        unpack2(pA01, eA0, eA1); unpack2(pA23, eA2, eA3); unpack2(pA4e, eA4, eAc2);
        float eB0, eB1, eB2, eB3, eB4, eBc2;
        unpack2(pB01, eB0, eB1); unpack2(pB23, eB2, eB3); unpack2(pB4e, eB4, eBc2);

        // ---- gates + messages, edge A --------------------------------------
        {
            float eh = ((c == 0) ? eA0 : (c == 1) ? eA1 : (c == 2) ? eA2 : eA3) + behc;
            float gate = fast_sigmoid(kA + qvA.x + 2.f * eh);
            float msg  = gate * (qvA.y + eh);
            float m1 = __shfl_sync(0xffffffffu, msg, 1, 4);
            float m2 = __shfl_sync(0xffffffffu, msg, 2, 4);
            float m3 = __shfl_sync(0xffffffffu, msg, 3, 4);
            if (c == 3) {
                float eh4 = eA4 + beh4;
                float g4  = fast_sigmoid(k4A + qv4A.x + 2.f * eh4);
                atomicAdd(&agf[(size_t)dstA * 8 + 4], g4 * (qv4A.y + eh4));
            } else if (c == 0) {
                g_e2[e] = eAc2 + bec2;
                atomicAdd(&g_aggv[(size_t)dstA * 2], make_float4(msg, m1, m2, m3));
            }
        }
        // ---- gates + messages, edge B --------------------------------------
        if (hb) {
            float eh = ((c == 0) ? eB0 : (c == 1) ? eB1 : (c == 2) ? eB2 : eB3) + behc;
            float gate = fast_sigmoid(kB + qvB.x + 2.f * eh);
            float msg  = gate * (qvB.y + eh);
            float m1 = __shfl_sync(0xffffffffu, msg, 1, 4);
            float m2 = __shfl_sync(0xffffffffu, msg, 2, 4);
            float m3 = __shfl_sync(0xffffffffu, msg, 3, 4);
            if (c == 3) {
                float eh4 = eB4 + beh4;
                float g4  = fast_sigmoid(k4B + qv4B.x + 2.f * eh4);
                atomicAdd(&agf[(size_t)dstB * 8 + 4], g4 * (qv4B.y + eh4));
            } else if (c == 0) {
                g_e2[eb] = eBc2 + bec2;
                atomicAdd(&g_aggv[(size_t)dstB * 2], make_float4(msg, m1, m2, m3));
            }
        }
    }
}

// ---------------------------------------------------------------------------
__device__ __forceinline__ void grid_barrier(unsigned target)
{
    __syncthreads();
    if (threadIdx.x == 0) {
        __threadfence();
        atomicAdd(&g_bar, 1u);
        while (*(volatile unsigned*)&g_bar < target) { }
        __threadfence();
    }
    __syncthreads();
}

// ---------------------------------------------------------------------------
// K3: fused tail — gnorm stats -> A,B -> norm+relu+proj2 -> edge pass2 ->
// final sigmoid, separated by grid barriers.
__global__ __launch_bounds__(NT3) void fused_tail(
    const int* __restrict__ batch, const int* __restrict__ ei,
    const float* __restrict__ gw, const float* __restrict__ gb,
    const float* __restrict__ gms,
    const float* __restrict__ Wk2, const float* __restrict__ bk2,
    const float* __restrict__ Wq2, const float* __restrict__ bq2,
    const float* __restrict__ Wv2, const float* __restrict__ bv2,
    const float* __restrict__ Ws2, const float* __restrict__ b2,
    float* __restrict__ out, int N, int E)
{
    __shared__ float ssum[NGRP * 5], ssq[NGRP * 5], scnt[NGRP];
    __shared__ float sA[NGRP * 5], sB[NGRP * 5];

    int tid  = threadIdx.x;
    int lane = tid & 31;
    const float* agf = (const float*)g_aggv;

    // ---- phase 1: group statistics -----------------------------------------
    for (int i = tid; i < NGRP * 5; i += NT3) { ssum[i] = 0.f; ssq[i] = 0.f; }
    if (tid < NGRP) scnt[tid] = 0.f;
    __syncthreads();

#pragma unroll
    for (int it = 0; it < 2; it++) {
        int n = blockIdx.x * NT3 + tid + it * GS3;
        bool valid = n < N;
        unsigned act = __ballot_sync(0xffffffffu, valid);
        if (act == 0) continue;

        int g  = valid ? __ldg(&batch[n]) : 0;
        int g0 = __shfl_sync(0xffffffffu, g, 0);
        bool uni = __all_sync(0xffffffffu, valid && (g == g0));

        float v[5];
        float4 v4 = valid ? __ldg((const float4*)(agf + (size_t)n * 8))
                          : make_float4(0.f, 0.f, 0.f, 0.f);
        float  v5 = valid ? __ldg(agf + (size_t)n * 8 + 4) : 0.f;
        v[0] = v4.x; v[1] = v4.y; v[2] = v4.z; v[3] = v4.w; v[4] = v5;

        if (uni) {
#pragma unroll
            for (int h = 0; h < 5; h++) {
                float sv = v[h], sq = v[h] * v[h];
#pragma unroll
                for (int off = 16; off > 0; off >>= 1) {
                    sv += __shfl_xor_sync(0xffffffffu, sv, off);
                    sq += __shfl_xor_sync(0xffffffffu, sq, off);
                }
                if (lane == 0) {
                    atomicAdd(&ssum[g0 * 5 + h], sv);
                    atomicAdd(&ssq[g0 * 5 + h], sq);
                }
            }
            if (lane == 0) atomicAdd(&scnt[g0], 32.f);
        } else if (valid) {
#pragma unroll
            for (int h = 0; h < 5; h++) {
                atomicAdd(&ssum[g * 5 + h], v[h]);
                atomicAdd(&ssq[g * 5 + h], v[h] * v[h]);
            }
            atomicAdd(&scnt[g], 1.f);
        }
    }
    __syncthreads();
    for (int i = tid; i < NGRP * 5; i += NT3) {
        atomicAdd(&g_gsum[i], ssum[i]);
        atomicAdd(&g_gsq[i],  ssq[i]);
    }
    if (tid < NGRP) atomicAdd(&g_gcnt[tid], scnt[tid]);

    grid_barrier(1u * NB3);

    // ---- phase 2: per-group affine ------------------------------------------
    if (tid < NGRP * 5) {
        int g = tid / 5, h = tid % 5;
        float cnt  = fmaxf(__ldcg(&g_gcnt[g]), 1.f);
        float mean = __ldcg(&g_gsum[tid]) / cnt;
        float ex2  = __ldcg(&g_gsq[tid])  / cnt;
        float ms   = __ldg(&gms[h]);
        float d    = mean * ms;
        float var  = ex2 - 2.f * d * mean + d * d;
        float inv  = rsqrtf(var + 1e-5f);
        float wv   = __ldg(&gw[h]);
        sA[tid] = wv * inv;
        sB[tid] = __ldg(&gb[h]) - wv * inv * d;
    }
    __syncthreads();

    // ---- phase 3: norm + relu + conv2 node projections ----------------------
    float k2b = __ldg(bk2), q2b = __ldg(bq2), v2b = __ldg(bv2), s2b = __ldg(b2);
    float wk[5], wq[5], wv5[5], wsk[5];
#pragma unroll
    for (int h = 0; h < 5; h++) {
        wk[h]  = __ldg(&Wk2[h]); wq[h]  = __ldg(&Wq2[h]);
        wv5[h] = __ldg(&Wv2[h]); wsk[h] = __ldg(&Ws2[h]);
    }
#pragma unroll
    for (int it = 0; it < 2; it++) {
        int n = blockIdx.x * NT3 + tid + it * GS3;
        if (n < N) {
            int g = __ldg(&batch[n]);
            float4 a4 = __ldg((const float4*)(agf + (size_t)n * 8));
            float  a5 = __ldg(agf + (size_t)n * 8 + 4);
            float av[5] = {a4.x, a4.y, a4.z, a4.w, a5};
            float k2 = k2b, q2 = q2b, v2 = v2b, s2 = s2b;
#pragma unroll
            for (int h = 0; h < 5; h++) {
                float hv = fmaxf(fmaf(sA[g * 5 + h], av[h], sB[g * 5 + h]), 0.f);
                k2 = fmaf(hv, wk[h],  k2);
                q2 = fmaf(hv, wq[h],  q2);
                v2 = fmaf(hv, wv5[h], v2);
                s2 = fmaf(hv, wsk[h], s2);
            }
            g_kqv2[n] = make_float4(k2, q2, v2, 0.f);
            out[n]    = s2;
        }
    }

    grid_barrier(2u * NB3);

    // ---- phase 4: conv2 edge pass (2-wide for MLP) ---------------------------
    {
        int base = blockIdx.x * NT3 + tid;
        for (int e = base; e < E; e += 2 * GS3) {
            int eb = e + GS3;
            bool hb = eb < E;
            int sa = __ldg(&ei[e]),  da = __ldg(&ei[E + e]);
            int sb = hb ? __ldg(&ei[eb]) : 0;
            int db = hb ? __ldg(&ei[E + eb]) : 0;
            float eva = __ldg(&g_e2[e]);
            float evb = hb ? __ldg(&g_e2[eb]) : 0.f;
            float4 da4 = __ldcg(&g_kqv2[da]);
            float4 sa4 = __ldcg(&g_kqv2[sa]);
            float4 db4 = hb ? __ldcg(&g_kqv2[db]) : make_float4(0, 0, 0, 0);
            float4 sb4 = hb ? __ldcg(&g_kqv2[sb]) : make_float4(0, 0, 0, 0);
            float ga = fast_sigmoid(da4.x + sa4.y + 2.f * eva);
            atomicAdd(&out[da], ga * (sa4.z + eva));
            if (hb) {
                float gbv = fast_sigmoid(db4.x + sb4.y + 2.f * evb);
                atomicAdd(&out[db], gbv * (sb4.z + evb));
            }
        }
    }

    grid_barrier(3u * NB3);

    // ---- phase 5: final sigmoid ----------------------------------------------
#pragma unroll
    for (int it = 0; it < 2; it++) {
        int n = blockIdx.x * NT3 + tid + it * GS3;
        if (n < N) out[n] = fast_sigmoid(__ldcg(&out[n]));
    }
}

// ---------------------------------------------------------------------------
extern "C" void kernel_launch(void* const* d_in, const int* in_sizes, int n_in,
                              void* d_out, int out_size)
{
    const float* x     = (const float*)d_in[0];
    const float* eatt  = (const float*)d_in[1];
    const int*   ei    = (const int*)d_in[2];
    const int*   batch = (const int*)d_in[3];
    const float* Wk1 = (const float*)d_in[4];
    const float* bk1 = (const float*)d_in[5];
    const float* Wq1 = (const float*)d_in[6];
    const float* bq1 = (const float*)d_in[7];
    const float* Wv1 = (const float*)d_in[8];
    const float* bv1 = (const float*)d_in[9];
    const float* We1 = (const float*)d_in[10];
    const float* be1 = (const float*)d_in[11];
    const float* Ws1 = (const float*)d_in[12];
    const float* b1  = (const float*)d_in[13];
    const float* gw  = (const float*)d_in[14];
    const float* gb  = (const float*)d_in[15];
    const float* gms = (const float*)d_in[16];
    const float* Wk2 = (const float*)d_in[17];
    const float* bk2 = (const float*)d_in[18];
    const float* Wq2 = (const float*)d_in[19];
    const float* bq2 = (const float*)d_in[20];
    const float* Wv2 = (const float*)d_in[21];
    const float* bv2 = (const float*)d_in[22];
    const float* We2 = (const float*)d_in[23];
    const float* be2 = (const float*)d_in[24];
    const float* Ws2 = (const float*)d_in[25];
    const float* b2  = (const float*)d_in[26];
    float* out = (float*)d_out;

    int N = in_sizes[3];
    int E = in_sizes[2] / 2;
    if (N > NMAX) N = NMAX;
    if (E > EMAX) E = EMAX;

    node_proj1<<<296, 256>>>(x, Wk1, bk1, Wq1, bq1, Wv1, bv1, Ws1, b1, N);
    edge_pass1<<<1184, 256>>>(eatt, ei, We1, be1, We2, be2, E);
    fused_tail<<<NB3, NT3>>>(batch, ei, gw, gb, gms,
                             Wk2, bk2, Wq2, bq2, Wv2, bv2, Ws2, b2,
                             out, N, E);
}

// round 7
// speedup vs baseline: 1.2034x; 1.0173x over previous
#include <cuda_runtime.h>

// ---------------- problem constants ----------------------------------------
#define NMAX 100000
#define EMAX 1600000
#define NGRP 64
#define NODEB 148         // hetero K1: node-GEMM blocks
#define GEMVB 148         // hetero K1: edge-GEMV blocks
#define NB3  148          // fused-tail persistent grid
#define NT3  512
#define GS3  (NB3 * NT3)

// ---------------- scratch (__device__ globals) -----------------------------
__device__ float2   g_kqvv[NMAX * 16];   // per node 32 f: k0..4 @0, (q_s,v_s) @8+2s
__device__ float4   g_aggv[NMAX * 2];    // per node 8 f: conv1 agg in [0..5)
__device__ float4   g_e1a[EMAX];         // per-edge conv1 proj h0..h3 (+bias)
__device__ float    g_e1b[EMAX];         // per-edge conv1 proj h4 (+bias)
__device__ float    g_e2[EMAX];          // per-edge conv2 edge projection (+bias)
__device__ float4   g_kqv2[NMAX];        // conv2 node proj (k2,q2,v2,_)
__device__ float    g_gsum[NGRP * 5];
__device__ float    g_gsq[NGRP * 5];
__device__ float    g_gcnt[NGRP];
__device__ unsigned g_bar;               // grid barrier counter (reset by K1)

__device__ __forceinline__ float fast_sigmoid(float z) {
    return 1.0f / (1.0f + __expf(-z));
}

// ---- packed f32x2 helpers (ptxas won't emit FFMA2/FADD2 from C++) ---------
__device__ __forceinline__ unsigned long long pack2(float a, float b) {
    unsigned long long r;
    asm("mov.b64 %0, {%1, %2};" : "=l"(r) : "f"(a), "f"(b));
    return r;
}
__device__ __forceinline__ void unpack2(unsigned long long v, float& a, float& b) {
    asm("mov.b64 {%0, %1}, %2;" : "=f"(a), "=f"(b) : "l"(v));
}
__device__ __forceinline__ void fma2(unsigned long long& d,
                                     unsigned long long a, unsigned long long b) {
    asm("fma.rn.f32x2 %0, %1, %2, %0;" : "+l"(d) : "l"(a), "l"(b));
}
__device__ __forceinline__ unsigned long long add2(unsigned long long a,
                                                   unsigned long long b) {
    unsigned long long r;
    asm("add.rn.f32x2 %0, %1, %2;" : "=l"(r) : "l"(a), "l"(b));
    return r;
}

// ---------------------------------------------------------------------------
// K1 (heterogeneous): blocks [0,148) = conv1 node GEMM; blocks [148,296) =
// conv1/conv2 edge-attr GEMV. Independent work, co-resident on each SM
// (<=128 regs, 2 blocks/SM): the DRAM-bound GEMV stream hides the GEMM's
// latency gaps.
__global__ __launch_bounds__(256, 2) void k1_hetero(
    const float* __restrict__ x,
    const float* __restrict__ Wk, const float* __restrict__ bk,
    const float* __restrict__ Wq, const float* __restrict__ bq,
    const float* __restrict__ Wv, const float* __restrict__ bv,
    const float* __restrict__ Ws, const float* __restrict__ bs,
    const float* __restrict__ eatt,
    const float* __restrict__ We1, const float* __restrict__ be1,
    const float* __restrict__ We2, const float* __restrict__ be2,
    int N, int E)
{
    __shared__ __align__(16) float sbuf[5376];

    int tid  = threadIdx.x;
    int lane = tid & 31;
    int wid  = tid >> 5;

    if (blockIdx.x < NODEB) {
        // ================= node GEMM: warp pair per node ====================
        int pr = wid >> 1;        // pair 0..3
        int r  = wid & 1;         // role within pair

        if (blockIdx.x == 0) {
            for (int i = tid; i < NGRP * 5; i += 256) { g_gsum[i] = 0.f; g_gsq[i] = 0.f; }
            if (tid < NGRP) g_gcnt[tid] = 0.f;
            if (tid == 0)   g_bar = 0u;
        }

        for (int i = tid; i < 256 * 20; i += 256) {
            int c = i / 20, h = i % 20;
            float v;
            if (h < 5)       v = Wk[c * 5 + h];
            else if (h < 10) v = Wq[c * 5 + h - 5];
            else if (h < 15) v = Wv[c * 5 + h - 10];
            else             v = Ws[c * 5 + h - 15];
            sbuf[c * 21 + h] = v;
        }
        __syncthreads();

        unsigned long long w2[40];
#pragma unroll
        for (int i = 0; i < 4; i++) {
            int c = r * 128 + lane * 4 + i;
#pragma unroll
            for (int p = 0; p < 10; p++)
                w2[i * 10 + p] = pack2(sbuf[c * 21 + 2 * p], sbuf[c * 21 + 2 * p + 1]);
        }
        __syncthreads();                          // weights consumed: reuse sbuf

        float blane = 0.f;
        if (lane < 5)       blane = __ldg(&bk[lane]);
        else if (lane < 10) blane = __ldg(&bq[lane - 5]);
        else if (lane < 15) blane = __ldg(&bv[lane - 10]);
        else if (lane < 20) blane = __ldg(&bs[lane - 15]);

        float* myred = &sbuf[pr * 1320 + r * 640];
        float* hbuf  = &sbuf[pr * 1320 + 1280];   // 2x20 double-buffered handoff
        int bar_id = pr + 1;

        float* kq = (float*)g_kqvv;
        float* ag = (float*)g_aggv;

        int n    = blockIdx.x * 4 + pr;
        int step = NODEB * 4;
        int itp  = 0;

        float4 a0;
        if (n < N)
            a0 = __ldg((const float4*)(x + (size_t)n * 256 + r * 128 + lane * 4));

        while (n < N) {
            float4 cx = a0;
            int nn = n + step;
            if (nn < N)
                a0 = __ldg((const float4*)(x + (size_t)nn * 256 + r * 128 + lane * 4));

            unsigned long long acc2[10];
#pragma unroll
            for (int p = 0; p < 10; p++) acc2[p] = 0ull;

            float xv[4] = {cx.x, cx.y, cx.z, cx.w};
#pragma unroll
            for (int i = 0; i < 4; i++) {
                unsigned long long xa = pack2(xv[i], xv[i]);
#pragma unroll
                for (int p = 0; p < 10; p++)
                    fma2(acc2[p], xa, w2[i * 10 + p]);
            }

            ulonglong2* dst2 = (ulonglong2*)(myred + lane * 20);
#pragma unroll
            for (int q = 0; q < 5; q++)
                dst2[q] = make_ulonglong2(acc2[2 * q], acc2[2 * q + 1]);
            __syncwarp();

            float redsum = 0.f;
            if (lane < 20) {
                float s0 = 0.f, s1 = 0.f;
#pragma unroll
                for (int l = 0; l < 32; l += 2) {
                    s0 += myred[(l + 0) * 20 + lane];
                    s1 += myred[(l + 1) * 20 + lane];
                }
                redsum = s0 + s1;
                if (r == 1) hbuf[itp * 20 + lane] = redsum;
            }
            asm volatile("bar.sync %0, %1;" :: "r"(bar_id), "r"(64) : "memory");

            if (r == 0 && lane < 20) {
                float val = redsum + hbuf[itp * 20 + lane] + blane;
                if (lane < 5)        kq[(size_t)n * 32 + lane] = val;
                else if (lane < 10)  kq[(size_t)n * 32 + 8 + 2 * (lane - 5)] = val;
                else if (lane < 15)  kq[(size_t)n * 32 + 9 + 2 * (lane - 10)] = val;
                else                 ag[(size_t)n * 8 + (lane - 15)] = val;
            }
            itp ^= 1;
            n = nn;
        }
    } else {
        // ================= edge GEMV: 4 lanes/edge, 2-edge pipeline =========
        int c   = tid & 3;
        int grp = (tid >> 2) & 7;

        unsigned long long w01[8], w23[8], w4e[8];
#pragma unroll
        for (int i = 0; i < 8; i++) {
            int col = c * 8 + i;
            w01[i] = pack2(__ldg(&We1[col * 5 + 0]), __ldg(&We1[col * 5 + 1]));
            w23[i] = pack2(__ldg(&We1[col * 5 + 2]), __ldg(&We1[col * 5 + 3]));
            w4e[i] = pack2(__ldg(&We1[col * 5 + 4]), __ldg(&We2[col]));
        }
        float b0 = __ldg(&be1[0]), b1 = __ldg(&be1[1]), b2 = __ldg(&be1[2]);
        float b3 = __ldg(&be1[3]), b4 = __ldg(&be1[4]);
        float bec2 = __ldg(be2);

        const float4* ea4 = (const float4*)eatt;
        const int WTOT  = GEMVB * 8;              // 1184 warps
        const int estep = 2 * WTOT * 8;
        int wg = (blockIdx.x - NODEB) * 8 + wid;

        for (int ew = wg * 8; ew < E; ew += estep) {
            int eA = ew + grp;
            int eB = ew + WTOT * 8 + grp;
            bool vA = eA < E, vB = eB < E;
            size_t iA = (size_t)(vA ? eA : 0);
            size_t iB = (size_t)(vB ? eB : 0);

            float4 a0 = __ldg(&ea4[iA * 8 + c * 2]);
            float4 a1 = __ldg(&ea4[iA * 8 + c * 2 + 1]);
            float4 q0 = __ldg(&ea4[iB * 8 + c * 2]);
            float4 q1 = __ldg(&ea4[iB * 8 + c * 2 + 1]);

            unsigned long long pA01 = 0ull, pA23 = 0ull, pA4e = 0ull;
            unsigned long long pB01 = 0ull, pB23 = 0ull, pB4e = 0ull;
            float xsA[8] = {a0.x, a0.y, a0.z, a0.w, a1.x, a1.y, a1.z, a1.w};
            float xsB[8] = {q0.x, q0.y, q0.z, q0.w, q1.x, q1.y, q1.z, q1.w};
#pragma unroll
            for (int i = 0; i < 8; i++) {
                unsigned long long xa = pack2(xsA[i], xsA[i]);
                unsigned long long xb = pack2(xsB[i], xsB[i]);
                fma2(pA01, xa, w01[i]); fma2(pA23, xa, w23[i]); fma2(pA4e, xa, w4e[i]);
                fma2(pB01, xb, w01[i]); fma2(pB23, xb, w23[i]); fma2(pB4e, xb, w4e[i]);
            }
#pragma unroll
            for (int off = 2; off > 0; off >>= 1) {
                pA01 = add2(pA01, __shfl_xor_sync(0xffffffffu, pA01, off, 4));
                pA23 = add2(pA23, __shfl_xor_sync(0xffffffffu, pA23, off, 4));
                pA4e = add2(pA4e, __shfl_xor_sync(0xffffffffu, pA4e, off, 4));
                pB01 = add2(pB01, __shfl_xor_sync(0xffffffffu, pB01, off, 4));
                pB23 = add2(pB23, __shfl_xor_sync(0xffffffffu, pB23, off, 4));
                pB4e = add2(pB4e, __shfl_xor_sync(0xffffffffu, pB4e, off, 4));
            }
            float eA0, eA1, eA2, eA3, eA4, eAc2;
            unpack2(pA01, eA0, eA1); unpack2(pA23, eA2, eA3); unpack2(pA4e, eA4, eAc2);
            float eB0, eB1, eB2, eB3, eB4, eBc2;
            unpack2(pB01, eB0, eB1); unpack2(pB23, eB2, eB3); unpack2(pB4e, eB4, eBc2);

            if (vA) {
                if (c == 0)      g_e1a[eA] = make_float4(eA0 + b0, eA1 + b1, eA2 + b2, eA3 + b3);
                else if (c == 1) g_e1b[eA] = eA4 + b4;
                else if (c == 2) g_e2[eA]  = eAc2 + bec2;
            }
            if (vB) {
                if (c == 0)      g_e1a[eB] = make_float4(eB0 + b0, eB1 + b1, eB2 + b2, eB3 + b3);
                else if (c == 1) g_e1b[eB] = eB4 + b4;
                else if (c == 2) g_e2[eB]  = eBc2 + bec2;
            }
        }
    }
}

// ---------------------------------------------------------------------------
// K2: conv1 gate + aggregate. 4 lanes/edge, 2-edge pipeline, warp-uniform loop.
// Lane c handles feature c; lane 3 also feature 4. One float4 RED + one
// scalar RED per edge.
__global__ __launch_bounds__(256) void gate_agg(const int* __restrict__ ei, int E)
{
    int tid = threadIdx.x;
    int c   = tid & 3;
    int grp = (tid >> 2) & 7;
    int wid = tid >> 5;

    const float* kqf = (const float*)g_kqvv;
    float*       agf = (float*)g_aggv;

    int WTOT  = gridDim.x * 8;
    int estep = 2 * WTOT * 8;
    int wg = blockIdx.x * 8 + wid;

    for (int ew = wg * 8; ew < E; ew += estep) {
        int eA = ew + grp;
        int eB = ew + WTOT * 8 + grp;
        bool vA = eA < E, vB = eB < E;
        size_t iA = (size_t)(vA ? eA : 0);
        size_t iB = (size_t)(vB ? eB : 0);

        int sA = __ldg(&ei[iA]), dA = __ldg(&ei[E + iA]);
        int sB = __ldg(&ei[iB]), dB = __ldg(&ei[E + iB]);

        float4 e1A = __ldg(&g_e1a[iA]);
        float4 e1B = __ldg(&g_e1a[iB]);

        float  kA  = __ldg(&kqf[(size_t)dA * 32 + c]);
        float2 qvA = __ldg(&g_kqvv[(size_t)sA * 16 + 4 + c]);
        float  kB  = __ldg(&kqf[(size_t)dB * 32 + c]);
        float2 qvB = __ldg(&g_kqvv[(size_t)sB * 16 + 4 + c]);

        float e4A = 0.f, e4B = 0.f, k4A = 0.f, k4B = 0.f;
        float2 qv4A = make_float2(0.f, 0.f), qv4B = make_float2(0.f, 0.f);
        if (c == 3) {
            e4A  = __ldg(&g_e1b[iA]);
            k4A  = __ldg(&kqf[(size_t)dA * 32 + 4]);
            qv4A = __ldg(&g_kqvv[(size_t)sA * 16 + 8]);
            e4B  = __ldg(&g_e1b[iB]);
            k4B  = __ldg(&kqf[(size_t)dB * 32 + 4]);
            qv4B = __ldg(&g_kqvv[(size_t)sB * 16 + 8]);
        }

        // ---- edge A ----
        {
            float eh = (c == 0) ? e1A.x : (c == 1) ? e1A.y : (c == 2) ? e1A.z : e1A.w;
            float gate = fast_sigmoid(kA + qvA.x + 2.f * eh);
            float msg  = gate * (qvA.y + eh);
            float m1 = __shfl_sync(0xffffffffu, msg, 1, 4);
            float m2 = __shfl_sync(0xffffffffu, msg, 2, 4);
            float m3 = __shfl_sync(0xffffffffu, msg, 3, 4);
            if (vA) {
                if (c == 0)
                    atomicAdd(&g_aggv[(size_t)dA * 2], make_float4(msg, m1, m2, m3));
                else if (c == 3) {
                    float g4 = fast_sigmoid(k4A + qv4A.x + 2.f * e4A);
                    atomicAdd(&agf[(size_t)dA * 8 + 4], g4 * (qv4A.y + e4A));
                }
            }
        }
        // ---- edge B ----
        {
            float eh = (c == 0) ? e1B.x : (c == 1) ? e1B.y : (c == 2) ? e1B.z : e1B.w;
            float gate = fast_sigmoid(kB + qvB.x + 2.f * eh);
            float msg  = gate * (qvB.y + eh);
            float m1 = __shfl_sync(0xffffffffu, msg, 1, 4);
            float m2 = __shfl_sync(0xffffffffu, msg, 2, 4);
            float m3 = __shfl_sync(0xffffffffu, msg, 3, 4);
            if (vB) {
                if (c == 0)
                    atomicAdd(&g_aggv[(size_t)dB * 2], make_float4(msg, m1, m2, m3));
                else if (c == 3) {
                    float g4 = fast_sigmoid(k4B + qv4B.x + 2.f * e4B);
                    atomicAdd(&agf[(size_t)dB * 8 + 4], g4 * (qv4B.y + e4B));
                }
            }
        }
    }
}

// ---------------------------------------------------------------------------
__device__ __forceinline__ void grid_barrier(unsigned target)
{
    __syncthreads();
    if (threadIdx.x == 0) {
        __threadfence();
        atomicAdd(&g_bar, 1u);
        while (*(volatile unsigned*)&g_bar < target) { }
        __threadfence();
    }
    __syncthreads();
}

// ---------------------------------------------------------------------------
// K3: fused tail — gnorm stats -> A,B -> norm+relu+proj2 -> edge pass2 ->
// final sigmoid, separated by grid barriers.
__global__ __launch_bounds__(NT3) void fused_tail(
    const int* __restrict__ batch, const int* __restrict__ ei,
    const float* __restrict__ gw, const float* __restrict__ gb,
    const float* __restrict__ gms,
    const float* __restrict__ Wk2, const float* __restrict__ bk2,
    const float* __restrict__ Wq2, const float* __restrict__ bq2,
    const float* __restrict__ Wv2, const float* __restrict__ bv2,
    const float* __restrict__ Ws2, const float* __restrict__ b2,
    float* __restrict__ out, int N, int E)
{
    __shared__ float ssum[NGRP * 5], ssq[NGRP * 5], scnt[NGRP];
    __shared__ float sA[NGRP * 5], sB[NGRP * 5];

    int tid  = threadIdx.x;
    int lane = tid & 31;
    const float* agf = (const float*)g_aggv;

    // ---- phase 1: group statistics -----------------------------------------
    for (int i = tid; i < NGRP * 5; i += NT3) { ssum[i] = 0.f; ssq[i] = 0.f; }
    if (tid < NGRP) scnt[tid] = 0.f;
    __syncthreads();

#pragma unroll
    for (int it = 0; it < 2; it++) {
        int n = blockIdx.x * NT3 + tid + it * GS3;
        bool valid = n < N;
        unsigned act = __ballot_sync(0xffffffffu, valid);
        if (act == 0) continue;

        int g  = valid ? __ldg(&batch[n]) : 0;
        int g0 = __shfl_sync(0xffffffffu, g, 0);
        bool uni = __all_sync(0xffffffffu, valid && (g == g0));

        float v[5];
        float4 v4 = valid ? __ldg((const float4*)(agf + (size_t)n * 8))
                          : make_float4(0.f, 0.f, 0.f, 0.f);
        float  v5 = valid ? __ldg(agf + (size_t)n * 8 + 4) : 0.f;
        v[0] = v4.x; v[1] = v4.y; v[2] = v4.z; v[3] = v4.w; v[4] = v5;

        if (uni) {
#pragma unroll
            for (int h = 0; h < 5; h++) {
                float sv = v[h], sq = v[h] * v[h];
#pragma unroll
                for (int off = 16; off > 0; off >>= 1) {
                    sv += __shfl_xor_sync(0xffffffffu, sv, off);
                    sq += __shfl_xor_sync(0xffffffffu, sq, off);
                }
                if (lane == 0) {
                    atomicAdd(&ssum[g0 * 5 + h], sv);
                    atomicAdd(&ssq[g0 * 5 + h], sq);
                }
            }
            if (lane == 0) atomicAdd(&scnt[g0], 32.f);
        } else if (valid) {
#pragma unroll
            for (int h = 0; h < 5; h++) {
                atomicAdd(&ssum[g * 5 + h], v[h]);
                atomicAdd(&ssq[g * 5 + h], v[h] * v[h]);
            }
            atomicAdd(&scnt[g], 1.f);
        }
    }
    __syncthreads();
    for (int i = tid; i < NGRP * 5; i += NT3) {
        atomicAdd(&g_gsum[i], ssum[i]);
        atomicAdd(&g_gsq[i],  ssq[i]);
    }
    if (tid < NGRP) atomicAdd(&g_gcnt[tid], scnt[tid]);

    grid_barrier(1u * NB3);

    // ---- phase 2: per-group affine ------------------------------------------
    if (tid < NGRP * 5) {
        int g = tid / 5, h = tid % 5;
        float cnt  = fmaxf(__ldcg(&g_gcnt[g]), 1.f);
        float mean = __ldcg(&g_gsum[tid]) / cnt;
        float ex2  = __ldcg(&g_gsq[tid])  / cnt;
        float ms   = __ldg(&gms[h]);
        float d    = mean * ms;
        float var  = ex2 - 2.f * d * mean + d * d;
        float inv  = rsqrtf(var + 1e-5f);
        float wv   = __ldg(&gw[h]);
        sA[tid] = wv * inv;
        sB[tid] = __ldg(&gb[h]) - wv * inv * d;
    }
    __syncthreads();

    // ---- phase 3: norm + relu + conv2 node projections ----------------------
    float k2b = __ldg(bk2), q2b = __ldg(bq2), v2b = __ldg(bv2), s2b = __ldg(b2);
    float wk[5], wq[5], wv5[5], wsk[5];
#pragma unroll
    for (int h = 0; h < 5; h++) {
        wk[h]  = __ldg(&Wk2[h]); wq[h]  = __ldg(&Wq2[h]);
        wv5[h] = __ldg(&Wv2[h]); wsk[h] = __ldg(&Ws2[h]);
    }
#pragma unroll
    for (int it = 0; it < 2; it++) {
        int n = blockIdx.x * NT3 + tid + it * GS3;
        if (n < N) {
            int g = __ldg(&batch[n]);
            float4 a4 = __ldg((const float4*)(agf + (size_t)n * 8));
            float  a5 = __ldg(agf + (size_t)n * 8 + 4);
            float av[5] = {a4.x, a4.y, a4.z, a4.w, a5};
            float k2 = k2b, q2 = q2b, v2 = v2b, s2 = s2b;
#pragma unroll
            for (int h = 0; h < 5; h++) {
                float hv = fmaxf(fmaf(sA[g * 5 + h], av[h], sB[g * 5 + h]), 0.f);
                k2 = fmaf(hv, wk[h],  k2);
                q2 = fmaf(hv, wq[h],  q2);
                v2 = fmaf(hv, wv5[h], v2);
                s2 = fmaf(hv, wsk[h], s2);
            }
            g_kqv2[n] = make_float4(k2, q2, v2, 0.f);
            out[n]    = s2;
        }
    }

    grid_barrier(2u * NB3);

    // ---- phase 4: conv2 edge pass (2-wide for MLP) ---------------------------
    {
        int base = blockIdx.x * NT3 + tid;
        for (int e = base; e < E; e += 2 * GS3) {
            int eb = e + GS3;
            bool hb = eb < E;
            int sa = __ldg(&ei[e]),  da = __ldg(&ei[E + e]);
            int sb = hb ? __ldg(&ei[eb]) : 0;
            int db = hb ? __ldg(&ei[E + eb]) : 0;
            float eva = __ldg(&g_e2[e]);
            float evb = hb ? __ldg(&g_e2[eb]) : 0.f;
            float4 da4 = __ldcg(&g_kqv2[da]);
            float4 sa4 = __ldcg(&g_kqv2[sa]);
            float4 db4 = hb ? __ldcg(&g_kqv2[db]) : make_float4(0, 0, 0, 0);
            float4 sb4 = hb ? __ldcg(&g_kqv2[sb]) : make_float4(0, 0, 0, 0);
            float ga = fast_sigmoid(da4.x + sa4.y + 2.f * eva);
            atomicAdd(&out[da], ga * (sa4.z + eva));
            if (hb) {
                float gbv = fast_sigmoid(db4.x + sb4.y + 2.f * evb);
                atomicAdd(&out[db], gbv * (sb4.z + evb));
            }
        }
    }

    grid_barrier(3u * NB3);

    // ---- phase 5: final sigmoid ----------------------------------------------
#pragma unroll
    for (int it = 0; it < 2; it++) {
        int n = blockIdx.x * NT3 + tid + it * GS3;
        if (n < N) out[n] = fast_sigmoid(__ldcg(&out[n]));
    }
}

// ---------------------------------------------------------------------------
extern "C" void kernel_launch(void* const* d_in, const int* in_sizes, int n_in,
                              void* d_out, int out_size)
{
    const float* x     = (const float*)d_in[0];
    const float* eatt  = (const float*)d_in[1];
    const int*   ei    = (const int*)d_in[2];
    const int*   batch = (const int*)d_in[3];
    const float* Wk1 = (const float*)d_in[4];
    const float* bk1 = (const float*)d_in[5];
    const float* Wq1 = (const float*)d_in[6];
    const float* bq1 = (const float*)d_in[7];
    const float* Wv1 = (const float*)d_in[8];
    const float* bv1 = (const float*)d_in[9];
    const float* We1 = (const float*)d_in[10];
    const float* be1 = (const float*)d_in[11];
    const float* Ws1 = (const float*)d_in[12];
    const float* b1  = (const float*)d_in[13];
    const float* gw  = (const float*)d_in[14];
    const float* gb  = (const float*)d_in[15];
    const float* gms = (const float*)d_in[16];
    const float* Wk2 = (const float*)d_in[17];
    const float* bk2 = (const float*)d_in[18];
    const float* Wq2 = (const float*)d_in[19];
    const float* bq2 = (const float*)d_in[20];
    const float* Wv2 = (const float*)d_in[21];
    const float* bv2 = (const float*)d_in[22];
    const float* We2 = (const float*)d_in[23];
    const float* be2 = (const float*)d_in[24];
    const float* Ws2 = (const float*)d_in[25];
    const float* b2  = (const float*)d_in[26];
    float* out = (float*)d_out;

    int N = in_sizes[3];
    int E = in_sizes[2] / 2;
    if (N > NMAX) N = NMAX;
    if (E > EMAX) E = EMAX;

    k1_hetero<<<NODEB + GEMVB, 256>>>(x, Wk1, bk1, Wq1, bq1, Wv1, bv1, Ws1, b1,
                                      eatt, We1, be1, We2, be2, N, E);
    gate_agg<<<1184, 256>>>(ei, E);
    fused_tail<<<NB3, NT3>>>(batch, ei, gw, gb, gms,
                             Wk2, bk2, Wq2, bq2, Wv2, bv2, Ws2, b2,
                             out, N, E);
}